// round 8
// baseline (speedup 1.0000x reference)
#include <cuda_runtime.h>
#include <cuda_bf16.h>
#include <math.h>

// ---------------------------------------------------------------------------
// MAD_4612794876398  (round 7)  — "R3 fixed"
//  Single-image lenet, spatial-pair FFMA2 accumulators (zero pack MOVs),
//  overlapping input pairs stored PARITY-SPLIT in smem (conflict-free LDS.64),
//  at 24 warps/SM (256 thr x 3 blocks, ~70 regs). Image pairs built directly
//  from the global float4 loads via __shfl_down. Epilogue fused; tiny head.
// ---------------------------------------------------------------------------

#define FEAT   400
#define HID    12
#define NCLS   10
#define SMAX   8
#define NQ_MAX 1024
#define NR_MAX (NQ_MAX * SMAX)
#define BDIM   256
#define QPB    4

__device__ float g_x[NQ_MAX * HID];
__device__ float g_grad[NQ_MAX * HID * NCLS];
__device__ float g_rx[NR_MAX * HID];

typedef unsigned long long ull;

__device__ __forceinline__ ull pack2(float lo, float hi) {
    ull r; asm("mov.b64 %0, {%1, %2};" : "=l"(r) : "f"(lo), "f"(hi)); return r;
}
__device__ __forceinline__ void unpack2(ull v, float& lo, float& hi) {
    asm("mov.b64 {%0, %1}, %2;" : "=f"(lo), "=f"(hi) : "l"(v));
}
__device__ __forceinline__ ull fma2(ull a, ull b, ull c) {
    ull d; asm("fma.rn.f32x2 %0, %1, %2, %3;" : "=l"(d) : "l"(a), "l"(b), "l"(c));
    return d;
}

// dynamic smem layout (bytes):
//  [0,23808)        s_imgp  ull[3*32*31]  overlapping pairs, parity-split:
//                   row of 31 ull = [16 even-start c/2][15 odd-start 16+c/2]
//  [23808,27408)    s_wb1   ull[3*25*6]   (w,w) dup, 16B-aligned per k
//  [27408,46608)    s_wb2   ull[6*25*16]  (w,w) dup, 16B-aligned per k
//  [46608,55344)    s_p1p   ull[6*14*13]  pooled pairs, parity-split:
//                   row of 13 ull = [7 even c/2][6 odd 7+c/2]
//  [55344,60048)    s_p1    float[6*14*14] pooled scalars
//  [60048,61648)    s_feat  float[400]
//  [61648,61824)    s_bias2 ull[22]
#define OFF_WB1  23808
#define OFF_WB2  27408
#define OFF_P1P  46608
#define OFF_P1   55344
#define OFF_FEAT 60048
#define OFF_BIAS 61648
#define SMEM_TOTAL 61824

__global__ __launch_bounds__(BDIM, 3)
void lenet_kernel(const float* __restrict__ img,
                  const float* __restrict__ train,
                  const int*   __restrict__ refs,
                  const float* __restrict__ w1, const float* __restrict__ b1,
                  const float* __restrict__ w2, const float* __restrict__ b2,
                  const float* __restrict__ Wf, const float* __restrict__ bf,
                  const float* __restrict__ Wg, const float* __restrict__ bg,
                  int n_img)
{
    extern __shared__ char smem_raw[];
    ull*   s_imgp  = (ull*)  (smem_raw);
    ull*   s_wb1   = (ull*)  (smem_raw + OFF_WB1);
    ull*   s_wb2   = (ull*)  (smem_raw + OFF_WB2);
    ull*   s_p1p   = (ull*)  (smem_raw + OFF_P1P);
    float* s_p1    = (float*)(smem_raw + OFF_P1);
    float* s_feat  = (float*)(smem_raw + OFF_FEAT);
    ull*   s_bias2 = (ull*)  (smem_raw + OFF_BIAS);

    const int b = blockIdx.x;
    const int t = threadIdx.x;

    const float* src = (b < n_img)
        ? img + (size_t)b * 3072
        : train + (size_t)refs[b - n_img] * 3072;

    // ---- load image, build overlapping pairs in-flight (shfl for seam) ----
    {
        const float4* s4 = reinterpret_cast<const float4*>(src);
        #pragma unroll
        for (int it = 0; it < 3; it++) {
            int i = t + it * BDIM;               // 0..767
            float4 v = s4[i];
            float nx = __shfl_down_sync(0xFFFFFFFFu, v.x, 1);
            int icy = i >> 3;                    // row 0..95 (ic*32+y)
            int m   = i & 7;                     // float4 index within row
            ull* row = s_imgp + icy * 31;
            row[2 * m]          = pack2(v.x, v.y);   // pair c=4m   (even)
            row[16 + 2 * m]     = pack2(v.y, v.z);   // pair c=4m+1 (odd)
            row[2 * m + 1]      = pack2(v.z, v.w);   // pair c=4m+2 (even)
            if (m < 7)
                row[16 + 2 * m + 1] = pack2(v.w, nx); // pair c=4m+3 (odd)
        }
    }
    // ---- duplicated weights ----
    for (int i = t; i < 450; i += BDIM) {
        int oc = i % 6, r = i / 6, k = r % 25, ic = r / 25;
        float v = w1[oc * 75 + ic * 25 + k];
        s_wb1[(ic * 25 + k) * 6 + oc] = pack2(v, v);
    }
    for (int i = t; i < 2400; i += BDIM) {
        int oc = i % 16, r = i / 16, k = r % 25, ic = r / 25;
        float v = w2[oc * 150 + ic * 25 + k];
        s_wb2[(ic * 25 + k) * 16 + oc] = pack2(v, v);
    }
    if (t < 6)       s_bias2[t] = pack2(b1[t], b1[t]);
    else if (t < 22) s_bias2[t] = pack2(b2[t - 6], b2[t - 6]);
    __syncthreads();

    // ---- conv1 + relu + maxpool2 : 6 x 14 x 14 ----
    if (t < 196) {
        const int py = t / 14, px = t % 14;
        const int iy = 2 * py;

        ull aT[6], aB[6];
        #pragma unroll
        for (int oc = 0; oc < 6; oc++) { aT[oc] = s_bias2[oc]; aB[oc] = aT[oc]; }

        #pragma unroll
        for (int ic = 0; ic < 3; ic++) {
            const ull* rb = s_imgp + ic * 992;        // 32*31
            ull rT[5], rB[5];
            {   // pairs starting at col 2px+kx, kx=0..4, parity-split slots
                const ull* e = rb + iy * 31 + px;
                rT[0] = e[0]; rT[1] = e[16]; rT[2] = e[1]; rT[3] = e[17]; rT[4] = e[2];
            }
            #pragma unroll
            for (int ky = 0; ky < 5; ky++) {
                {
                    const ull* e = rb + (iy + ky + 1) * 31 + px;
                    rB[0] = e[0]; rB[1] = e[16]; rB[2] = e[1]; rB[3] = e[17]; rB[4] = e[2];
                }
                #pragma unroll
                for (int kx = 0; kx < 5; kx++) {
                    const ull* wrow = s_wb1 + (ic * 25 + ky * 5 + kx) * 6;
                    ulonglong2 w01 = *reinterpret_cast<const ulonglong2*>(wrow);
                    ulonglong2 w23 = *reinterpret_cast<const ulonglong2*>(wrow + 2);
                    ulonglong2 w45 = *reinterpret_cast<const ulonglong2*>(wrow + 4);
                    aT[0] = fma2(w01.x, rT[kx], aT[0]);
                    aB[0] = fma2(w01.x, rB[kx], aB[0]);
                    aT[1] = fma2(w01.y, rT[kx], aT[1]);
                    aB[1] = fma2(w01.y, rB[kx], aB[1]);
                    aT[2] = fma2(w23.x, rT[kx], aT[2]);
                    aB[2] = fma2(w23.x, rB[kx], aB[2]);
                    aT[3] = fma2(w23.y, rT[kx], aT[3]);
                    aB[3] = fma2(w23.y, rB[kx], aB[3]);
                    aT[4] = fma2(w45.x, rT[kx], aT[4]);
                    aB[4] = fma2(w45.x, rB[kx], aB[4]);
                    aT[5] = fma2(w45.y, rT[kx], aT[5]);
                    aB[5] = fma2(w45.y, rB[kx], aB[5]);
                }
                #pragma unroll
                for (int x = 0; x < 5; x++) rT[x] = rB[x];
            }
        }
        #pragma unroll
        for (int oc = 0; oc < 6; oc++) {
            float t0, t1, b0v, b1v;
            unpack2(aT[oc], t0, t1);
            unpack2(aB[oc], b0v, b1v);
            float m = fmaxf(fmaxf(t0, t1), fmaxf(b0v, b1v));
            s_p1[(oc * 14 + py) * 14 + px] = fmaxf(m, 0.0f);
        }
    }
    __syncthreads();

    // ---- build pooled overlapping pairs, parity-split ----
    for (int i = t; i < 6 * 14 * 13; i += BDIM) {
        int c = i % 13, r = i / 13;              // r = ic*14 + y
        const float* row = s_p1 + r * 14;
        int slot = (c & 1) ? (7 + (c >> 1)) : (c >> 1);
        s_p1p[r * 13 + slot] = pack2(row[c], row[c + 1]);
    }
    __syncthreads();

    // ---- conv2 + relu + maxpool2 : 16 x 5 x 5 = 400 ----
    if (t < 200) {
        const int j   = t & 7;                   // oc pair (j fastest: bcast inputs)
        const int pos = t >> 3;                  // 0..24
        const int py = pos / 5, px = pos % 5;
        const int iy = 2 * py;
        const int oc0 = 2 * j;

        ull aT0, aB0, aT1, aB1;
        aT0 = s_bias2[6 + oc0];     aB0 = aT0;
        aT1 = s_bias2[6 + oc0 + 1]; aB1 = aT1;

        #pragma unroll
        for (int ic = 0; ic < 6; ic++) {
            const ull* rb = s_p1p + ic * 182;    // 14*13
            ull rT[5], rB[5];
            {
                const ull* e = rb + iy * 13 + px;
                rT[0] = e[0]; rT[1] = e[7]; rT[2] = e[1]; rT[3] = e[8]; rT[4] = e[2];
            }
            #pragma unroll
            for (int ky = 0; ky < 5; ky++) {
                {
                    const ull* e = rb + (iy + ky + 1) * 13 + px;
                    rB[0] = e[0]; rB[1] = e[7]; rB[2] = e[1]; rB[3] = e[8]; rB[4] = e[2];
                }
                #pragma unroll
                for (int kx = 0; kx < 5; kx++) {
                    ulonglong2 w = *reinterpret_cast<const ulonglong2*>(
                        s_wb2 + (ic * 25 + ky * 5 + kx) * 16 + oc0);
                    aT0 = fma2(w.x, rT[kx], aT0);
                    aB0 = fma2(w.x, rB[kx], aB0);
                    aT1 = fma2(w.y, rT[kx], aT1);
                    aB1 = fma2(w.y, rB[kx], aB1);
                }
                #pragma unroll
                for (int x = 0; x < 5; x++) rT[x] = rB[x];
            }
        }
        float t0, t1, b0v, b1v, m;
        unpack2(aT0, t0, t1); unpack2(aB0, b0v, b1v);
        m = fmaxf(fmaxf(t0, t1), fmaxf(b0v, b1v));
        s_feat[oc0 * 25 + pos] = fmaxf(m, 0.0f);
        unpack2(aT1, t0, t1); unpack2(aB1, b0v, b1v);
        m = fmaxf(fmaxf(t0, t1), fmaxf(b0v, b1v));
        s_feat[(oc0 + 1) * 25 + pos] = fmaxf(m, 0.0f);
    }
    __syncthreads();

    // ---- epilogue: warp-cooperative 400-dots ----
    const int warp = t >> 5, lane = t & 31;
    const float4* f4 = reinterpret_cast<const float4*>(s_feat);
    const int nrows = (b < n_img) ? (HID * NCLS + HID) : HID;

    for (int d = warp; d < nrows; d += (BDIM >> 5)) {
        const float* wrow; float bias;
        if (b < n_img && d < HID * NCLS) { wrow = Wg + (size_t)d * FEAT; bias = bg[d]; }
        else {
            int h = (b < n_img) ? (d - HID * NCLS) : d;
            wrow = Wf + (size_t)h * FEAT; bias = bf[h];
        }
        const float4* w4 = reinterpret_cast<const float4*>(wrow);
        float acc = 0.0f;
        #pragma unroll
        for (int it = 0; it < 4; it++) {
            int e = lane + it * 32;
            if (e < 100) {
                float4 a = f4[e], w = w4[e];
                acc += a.x*w.x + a.y*w.y + a.z*w.z + a.w*w.w;
            }
        }
        #pragma unroll
        for (int o = 16; o > 0; o >>= 1)
            acc += __shfl_xor_sync(0xFFFFFFFFu, acc, o);
        if (lane == 0) {
            float v = acc + bias;
            if (b < n_img) {
                if (d < HID * NCLS) g_grad[(size_t)b * (HID * NCLS) + d] = v;
                else                g_x[(size_t)b * HID + (d - HID * NCLS)] = v;
            } else {
                g_rx[(size_t)(b - n_img) * HID + d] = v;
            }
        }
    }
}

// ---------------------------------------------------------------------------
// Head kernel: tiny combine
// ---------------------------------------------------------------------------
__global__ __launch_bounds__(128)
void head_kernel(const float* __restrict__ mem,
                 const int*   __restrict__ refs,
                 const float* __restrict__ Wm, const float* __restrict__ bm,
                 float* __restrict__ out, int n, int S)
{
    __shared__ float s_x[QPB][HID];
    __shared__ float s_g[QPB][HID * NCLS];
    __shared__ float s_diff[QPB][SMAX][HID];
    __shared__ float s_norm[QPB][SMAX];
    __shared__ float s_mem[QPB][SMAX][NCLS];
    __shared__ float s_logit[QPB][SMAX][NCLS];
    __shared__ float s_wm[NCLS * NCLS];
    __shared__ float s_bm[NCLS];
    __shared__ int   s_refs[QPB][SMAX];

    const int t = threadIdx.x;
    const int q0 = blockIdx.x * QPB;

    if (t < QPB * SMAX) {
        int ql = t / SMAX, s = t % SMAX;
        s_refs[ql][s] = refs[(size_t)(q0 + ql) * S + s];
    }
    if (t < QPB * HID) {
        int ql = t / HID, h = t % HID;
        s_x[ql][h] = g_x[(size_t)(q0 + ql) * HID + h];
    }
    for (int i = t; i < QPB * HID * NCLS; i += 128) {
        int ql = i / (HID * NCLS), d = i % (HID * NCLS);
        s_g[ql][d] = g_grad[(size_t)(q0 + ql) * (HID * NCLS) + d];
    }
    if (t < NCLS * NCLS) s_wm[t] = Wm[t];
    if (t < NCLS) s_bm[t] = bm[t];
    __syncthreads();

    for (int i = t; i < QPB * SMAX * NCLS; i += 128) {
        int ql = i / (SMAX * NCLS), r2 = i % (SMAX * NCLS);
        int s = r2 / NCLS, c = r2 % NCLS;
        s_mem[ql][s][c] = mem[(size_t)s_refs[ql][s] * NCLS + c];
    }
    if (t < QPB * SMAX) {
        int ql = t / SMAX, s = t % SMAX;
        float acc = 0.0f;
        #pragma unroll
        for (int h = 0; h < HID; h++) {
            float rx = g_rx[(size_t)((q0 + ql) * S + s) * HID + h];
            float dd = s_x[ql][h] - rx;
            s_diff[ql][s][h] = dd;
            acc += dd * dd;
        }
        s_norm[ql][s] = sqrtf(acc);
    }
    __syncthreads();

    for (int i = t; i < QPB * SMAX * NCLS; i += 128) {
        int ql = i / (SMAX * NCLS), r2 = i % (SMAX * NCLS);
        int s = r2 / NCLS, c = r2 % NCLS;
        float acc = s_bm[c];
        #pragma unroll
        for (int jj = 0; jj < NCLS; jj++)
            acc += s_wm[c * NCLS + jj] * s_mem[ql][s][jj];
        #pragma unroll
        for (int h = 0; h < HID; h++)
            acc += s_diff[ql][s][h] * s_g[ql][h * NCLS + c];
        s_logit[ql][s][c] = acc;
    }
    __syncthreads();

    if (t < QPB * NCLS) {
        int ql = t / NCLS, c = t % NCLS;
        float mx = -1e30f;
        for (int s = 0; s < S; s++) mx = fmaxf(mx, -s_norm[ql][s]);
        float se = 0.0f, acc = 0.0f;
        for (int s = 0; s < S; s++) {
            float e = expf(-s_norm[ql][s] - mx);
            se += e;
            acc += e * s_logit[ql][s][c];
        }
        out[(size_t)(q0 + ql) * NCLS + c] = acc / se;
    }
}

// ---------------------------------------------------------------------------
// launcher
// ---------------------------------------------------------------------------
extern "C" void kernel_launch(void* const* d_in, const int* in_sizes, int n_in,
                              void* d_out, int out_size)
{
    const float* img   = (const float*)d_in[0];
    const float* train = (const float*)d_in[1];
    const float* mem   = (const float*)d_in[2];
    const float* w1    = (const float*)d_in[3];
    const float* b1    = (const float*)d_in[4];
    const float* w2    = (const float*)d_in[5];
    const float* b2    = (const float*)d_in[6];
    const float* Wf    = (const float*)d_in[7];
    const float* bf    = (const float*)d_in[8];
    const float* Wg    = (const float*)d_in[9];
    const float* bg    = (const float*)d_in[10];
    const float* Wm    = (const float*)d_in[11];
    const float* bm    = (const float*)d_in[12];
    // d_in[13] = idx : unused
    const int*   refs  = (const int*)d_in[14];

    const int n = in_sizes[0] / (3 * 32 * 32);   // 1024
    const int S = in_sizes[14] / n;              // 8
    if (n > NQ_MAX || S != SMAX || (n % QPB) != 0) return;

    cudaFuncSetAttribute(lenet_kernel,
                         cudaFuncAttributeMaxDynamicSharedMemorySize, SMEM_TOTAL);

    const int ntot = n + n * S;                  // 9216
    lenet_kernel<<<ntot, BDIM, SMEM_TOTAL>>>(img, train, refs,
                                             w1, b1, w2, b2,
                                             Wf, bf, Wg, bg, n);
    head_kernel<<<n / QPB, 128>>>(mem, refs, Wm, bm, (float*)d_out, n, S);
}

// round 9
// speedup vs baseline: 1.5767x; 1.5767x over previous
#include <cuda_runtime.h>
#include <cuda_bf16.h>
#include <math.h>

// ---------------------------------------------------------------------------
// MAD_4612794876398  (round 8)
//  = round-2 lenet (262-us proven conv core, oc-pair FFMA2, 224thr x 3blk/SM)
//    + the independently-validated R3 epilogue fusion: query blocks compute
//    grad/x, ref blocks compute rx, no 400-float feature ever hits HBM,
//    and head_kernel shrinks to the tiny combine (30 -> ~11 us, measured).
// ---------------------------------------------------------------------------

#define FEAT   400
#define HID    12
#define NCLS   10
#define SMAX   8
#define NQ_MAX 1024
#define NR_MAX (NQ_MAX * SMAX)
#define BDIM   224
#define QPB    4

__device__ float g_x[NQ_MAX * HID];           // query Wf projections
__device__ float g_grad[NQ_MAX * HID * NCLS]; // query Wg projections
__device__ float g_rx[NR_MAX * HID];          // ref Wf projections

typedef unsigned long long ull;

__device__ __forceinline__ ull pack2(float lo, float hi) {
    ull r; asm("mov.b64 %0, {%1, %2};" : "=l"(r) : "f"(lo), "f"(hi)); return r;
}
__device__ __forceinline__ void unpack2(ull v, float& lo, float& hi) {
    asm("mov.b64 {%0, %1}, %2;" : "=f"(lo), "=f"(hi) : "l"(v));
}
__device__ __forceinline__ ull fma2(ull a, ull b, ull c) {
    ull d; asm("fma.rn.f32x2 %0, %1, %2, %3;" : "=l"(d) : "l"(a), "l"(b), "l"(c));
    return d;
}
__device__ __forceinline__ ull ld64(const float2* p) {
    return *reinterpret_cast<const ull*>(p);
}

// ---------------------------------------------------------------------------
// LeNet feature kernel: one block per image  (R2 conv core, unchanged)
// ---------------------------------------------------------------------------
__global__ __launch_bounds__(BDIM, 3)
void lenet_kernel(const float* __restrict__ img,
                  const float* __restrict__ train,
                  const int*   __restrict__ refs,
                  const float* __restrict__ w1, const float* __restrict__ b1,
                  const float* __restrict__ w2, const float* __restrict__ b2,
                  const float* __restrict__ Wf, const float* __restrict__ bf,
                  const float* __restrict__ Wg, const float* __restrict__ bg,
                  int n_img)
{
    __shared__ float  s_img[3][32][32];       // 3072
    __shared__ float2 s_wp1[3][25][3];        // (oc2j, oc2j+1) pairs
    __shared__ float2 s_wp2[6][25][8];
    __shared__ float  s_b1[6];
    __shared__ float  s_b2[16];
    __shared__ float  s_p1[6][14][14];
    __shared__ float  s_feat[FEAT];

    const int b = blockIdx.x;
    const int t = threadIdx.x;

    const float* src = (b < n_img)
        ? img + (size_t)b * 3072
        : train + (size_t)refs[b - n_img] * 3072;

    // load image: 768 float4
    {
        const float4* s4 = reinterpret_cast<const float4*>(src);
        float4* d4 = reinterpret_cast<float4*>(&s_img[0][0][0]);
        for (int i = t; i < 768; i += BDIM) d4[i] = s4[i];
    }
    // load packed weight pairs
    for (int i = t; i < 225; i += BDIM) {                // wp1: ic,k,j
        int ic = i / 75, r = i % 75, k = r / 3, j = r % 3;
        s_wp1[ic][k][j] = make_float2(w1[(2*j)     * 75 + ic * 25 + k],
                                      w1[(2*j + 1) * 75 + ic * 25 + k]);
    }
    for (int i = t; i < 1200; i += BDIM) {               // wp2: ic,k,j
        int ic = i / 200, r = i % 200, k = r / 8, j = r % 8;
        s_wp2[ic][k][j] = make_float2(w2[(2*j)     * 150 + ic * 25 + k],
                                      w2[(2*j + 1) * 150 + ic * 25 + k]);
    }
    if (t < 6)  s_b1[t] = b1[t];
    if (t < 16) s_b2[t] = b2[t];
    __syncthreads();

    // ---- conv1 + relu + maxpool2 : 6 x 14 x 14, FFMA2 over oc-pairs ----
    if (t < 196) {
        const int py = t / 14, px = t % 14;
        const int iy = 2 * py, ix = 2 * px;

        ull acc[3][4];
        #pragma unroll
        for (int j = 0; j < 3; j++) {
            ull bz = pack2(s_b1[2*j], s_b1[2*j + 1]);
            acc[j][0] = bz; acc[j][1] = bz; acc[j][2] = bz; acc[j][3] = bz;
        }
        #pragma unroll
        for (int ic = 0; ic < 3; ic++) {
            float in[6][6];
            #pragma unroll
            for (int r = 0; r < 6; r++)
                #pragma unroll
                for (int c = 0; c < 6; c++)
                    in[r][c] = s_img[ic][iy + r][ix + c];

            #pragma unroll
            for (int ky = 0; ky < 5; ky++) {
                #pragma unroll
                for (int kx = 0; kx < 5; kx++) {
                    const int k = ky * 5 + kx;
                    ull w0 = ld64(&s_wp1[ic][k][0]);
                    ull w1v = ld64(&s_wp1[ic][k][1]);
                    ull w2v = ld64(&s_wp1[ic][k][2]);

                    ull p = pack2(in[ky][kx], in[ky][kx]);
                    acc[0][0] = fma2(w0, p, acc[0][0]);
                    acc[1][0] = fma2(w1v, p, acc[1][0]);
                    acc[2][0] = fma2(w2v, p, acc[2][0]);

                    p = pack2(in[ky][kx+1], in[ky][kx+1]);
                    acc[0][1] = fma2(w0, p, acc[0][1]);
                    acc[1][1] = fma2(w1v, p, acc[1][1]);
                    acc[2][1] = fma2(w2v, p, acc[2][1]);

                    p = pack2(in[ky+1][kx], in[ky+1][kx]);
                    acc[0][2] = fma2(w0, p, acc[0][2]);
                    acc[1][2] = fma2(w1v, p, acc[1][2]);
                    acc[2][2] = fma2(w2v, p, acc[2][2]);

                    p = pack2(in[ky+1][kx+1], in[ky+1][kx+1]);
                    acc[0][3] = fma2(w0, p, acc[0][3]);
                    acc[1][3] = fma2(w1v, p, acc[1][3]);
                    acc[2][3] = fma2(w2v, p, acc[2][3]);
                }
            }
        }
        #pragma unroll
        for (int j = 0; j < 3; j++) {
            float a0l, a0h, a1l, a1h, a2l, a2h, a3l, a3h;
            unpack2(acc[j][0], a0l, a0h);
            unpack2(acc[j][1], a1l, a1h);
            unpack2(acc[j][2], a2l, a2h);
            unpack2(acc[j][3], a3l, a3h);
            float ml = fmaxf(fmaxf(a0l, a1l), fmaxf(a2l, a3l));
            float mh = fmaxf(fmaxf(a0h, a1h), fmaxf(a2h, a3h));
            s_p1[2*j    ][py][px] = fmaxf(ml, 0.0f);
            s_p1[2*j + 1][py][px] = fmaxf(mh, 0.0f);
        }
    }
    __syncthreads();

    // ---- conv2 + relu + maxpool2 : 16 x 5 x 5 = 400, (pos, oc-pair) ----
    if (t < 200) {
        const int pos = t >> 3;
        const int j   = t & 7;
        const int py = pos / 5, px = pos % 5;
        const int iy = 2 * py, ix = 2 * px;

        ull a0, a1, a2, a3;
        {
            ull bz = pack2(s_b2[2*j], s_b2[2*j + 1]);
            a0 = bz; a1 = bz; a2 = bz; a3 = bz;
        }
        #pragma unroll
        for (int ic = 0; ic < 6; ic++) {
            float in[6][6];
            #pragma unroll
            for (int r = 0; r < 6; r++)
                #pragma unroll
                for (int c = 0; c < 6; c++)
                    in[r][c] = s_p1[ic][iy + r][ix + c];

            #pragma unroll
            for (int ky = 0; ky < 5; ky++) {
                #pragma unroll
                for (int kx = 0; kx < 5; kx++) {
                    ull w = ld64(&s_wp2[ic][ky * 5 + kx][j]);
                    a0 = fma2(w, pack2(in[ky  ][kx  ], in[ky  ][kx  ]), a0);
                    a1 = fma2(w, pack2(in[ky  ][kx+1], in[ky  ][kx+1]), a1);
                    a2 = fma2(w, pack2(in[ky+1][kx  ], in[ky+1][kx  ]), a2);
                    a3 = fma2(w, pack2(in[ky+1][kx+1], in[ky+1][kx+1]), a3);
                }
            }
        }
        float a0l,a0h,a1l,a1h,a2l,a2h,a3l,a3h;
        unpack2(a0, a0l, a0h); unpack2(a1, a1l, a1h);
        unpack2(a2, a2l, a2h); unpack2(a3, a3l, a3h);
        float ml = fmaxf(fmaxf(a0l, a1l), fmaxf(a2l, a3l));
        float mh = fmaxf(fmaxf(a0h, a1h), fmaxf(a2h, a3h));
        s_feat[(2*j    ) * 25 + pos] = fmaxf(ml, 0.0f);
        s_feat[(2*j + 1) * 25 + pos] = fmaxf(mh, 0.0f);
    }
    __syncthreads();

    // ---- fused epilogue: warp-cooperative 400-dots (R3-validated) ----
    const int warp = t >> 5, lane = t & 31;
    const float4* f4 = reinterpret_cast<const float4*>(s_feat);
    const int nrows = (b < n_img) ? (HID * NCLS + HID) : HID;

    for (int d = warp; d < nrows; d += (BDIM >> 5)) {
        const float* wrow; float bias;
        if (b < n_img && d < HID * NCLS) { wrow = Wg + (size_t)d * FEAT; bias = bg[d]; }
        else {
            int h = (b < n_img) ? (d - HID * NCLS) : d;
            wrow = Wf + (size_t)h * FEAT; bias = bf[h];
        }
        const float4* w4 = reinterpret_cast<const float4*>(wrow);
        float acc = 0.0f;
        #pragma unroll
        for (int it = 0; it < 4; it++) {
            int e = lane + it * 32;
            if (e < 100) {
                float4 a = f4[e], w = w4[e];
                acc += a.x*w.x + a.y*w.y + a.z*w.z + a.w*w.w;
            }
        }
        #pragma unroll
        for (int o = 16; o > 0; o >>= 1)
            acc += __shfl_xor_sync(0xFFFFFFFFu, acc, o);
        if (lane == 0) {
            float v = acc + bias;
            if (b < n_img) {
                if (d < HID * NCLS) g_grad[(size_t)b * (HID * NCLS) + d] = v;
                else                g_x[(size_t)b * HID + (d - HID * NCLS)] = v;
            } else {
                g_rx[(size_t)(b - n_img) * HID + d] = v;
            }
        }
    }
}

// ---------------------------------------------------------------------------
// Head kernel: tiny combine (R3-validated, ~11 us)
// ---------------------------------------------------------------------------
__global__ __launch_bounds__(128)
void head_kernel(const float* __restrict__ mem,
                 const int*   __restrict__ refs,
                 const float* __restrict__ Wm, const float* __restrict__ bm,
                 float* __restrict__ out, int n, int S)
{
    __shared__ float s_x[QPB][HID];
    __shared__ float s_g[QPB][HID * NCLS];
    __shared__ float s_diff[QPB][SMAX][HID];
    __shared__ float s_norm[QPB][SMAX];
    __shared__ float s_mem[QPB][SMAX][NCLS];
    __shared__ float s_logit[QPB][SMAX][NCLS];
    __shared__ float s_wm[NCLS * NCLS];
    __shared__ float s_bm[NCLS];
    __shared__ int   s_refs[QPB][SMAX];

    const int t = threadIdx.x;
    const int q0 = blockIdx.x * QPB;

    if (t < QPB * SMAX) {
        int ql = t / SMAX, s = t % SMAX;
        s_refs[ql][s] = refs[(size_t)(q0 + ql) * S + s];
    }
    if (t < QPB * HID) {
        int ql = t / HID, h = t % HID;
        s_x[ql][h] = g_x[(size_t)(q0 + ql) * HID + h];
    }
    for (int i = t; i < QPB * HID * NCLS; i += 128) {
        int ql = i / (HID * NCLS), d = i % (HID * NCLS);
        s_g[ql][d] = g_grad[(size_t)(q0 + ql) * (HID * NCLS) + d];
    }
    if (t < NCLS * NCLS) s_wm[t] = Wm[t];
    if (t < NCLS) s_bm[t] = bm[t];
    __syncthreads();

    for (int i = t; i < QPB * SMAX * NCLS; i += 128) {
        int ql = i / (SMAX * NCLS), r2 = i % (SMAX * NCLS);
        int s = r2 / NCLS, c = r2 % NCLS;
        s_mem[ql][s][c] = mem[(size_t)s_refs[ql][s] * NCLS + c];
    }
    if (t < QPB * SMAX) {
        int ql = t / SMAX, s = t % SMAX;
        float acc = 0.0f;
        #pragma unroll
        for (int h = 0; h < HID; h++) {
            float rx = g_rx[(size_t)((q0 + ql) * S + s) * HID + h];
            float dd = s_x[ql][h] - rx;
            s_diff[ql][s][h] = dd;
            acc += dd * dd;
        }
        s_norm[ql][s] = sqrtf(acc);
    }
    __syncthreads();

    for (int i = t; i < QPB * SMAX * NCLS; i += 128) {
        int ql = i / (SMAX * NCLS), r2 = i % (SMAX * NCLS);
        int s = r2 / NCLS, c = r2 % NCLS;
        float acc = s_bm[c];
        #pragma unroll
        for (int jj = 0; jj < NCLS; jj++)
            acc += s_wm[c * NCLS + jj] * s_mem[ql][s][jj];
        #pragma unroll
        for (int h = 0; h < HID; h++)
            acc += s_diff[ql][s][h] * s_g[ql][h * NCLS + c];
        s_logit[ql][s][c] = acc;
    }
    __syncthreads();

    if (t < QPB * NCLS) {
        int ql = t / NCLS, c = t % NCLS;
        float mx = -1e30f;
        for (int s = 0; s < S; s++) mx = fmaxf(mx, -s_norm[ql][s]);
        float se = 0.0f, acc = 0.0f;
        for (int s = 0; s < S; s++) {
            float e = expf(-s_norm[ql][s] - mx);
            se += e;
            acc += e * s_logit[ql][s][c];
        }
        out[(size_t)(q0 + ql) * NCLS + c] = acc / se;
    }
}

// ---------------------------------------------------------------------------
// launcher
// ---------------------------------------------------------------------------
extern "C" void kernel_launch(void* const* d_in, const int* in_sizes, int n_in,
                              void* d_out, int out_size)
{
    const float* img   = (const float*)d_in[0];
    const float* train = (const float*)d_in[1];
    const float* mem   = (const float*)d_in[2];
    const float* w1    = (const float*)d_in[3];
    const float* b1    = (const float*)d_in[4];
    const float* w2    = (const float*)d_in[5];
    const float* b2    = (const float*)d_in[6];
    const float* Wf    = (const float*)d_in[7];
    const float* bf    = (const float*)d_in[8];
    const float* Wg    = (const float*)d_in[9];
    const float* bg    = (const float*)d_in[10];
    const float* Wm    = (const float*)d_in[11];
    const float* bm    = (const float*)d_in[12];
    // d_in[13] = idx : unused by the reference computation
    const int*   refs  = (const int*)d_in[14];

    const int n = in_sizes[0] / (3 * 32 * 32);   // 1024
    const int S = in_sizes[14] / n;              // 8
    if (n > NQ_MAX || S != SMAX || (n % QPB) != 0) return;

    const int ntot = n + n * S;                  // 9216
    lenet_kernel<<<ntot, BDIM>>>(img, train, refs, w1, b1, w2, b2,
                                 Wf, bf, Wg, bg, n);
    head_kernel<<<n / QPB, 128>>>(mem, refs, Wm, bm, (float*)d_out, n, S);
}

// round 10
// speedup vs baseline: 2.4157x; 1.5321x over previous
#include <cuda_runtime.h>
#include <cuda_bf16.h>
#include <math.h>

// ---------------------------------------------------------------------------
// MAD_4612794876398  (round 9)
//  = round-2 kernel EXACTLY (262-us best: lenet conv core + ref-only Wf
//    epilogue, separate head doing the Wg/Wf projections), with ONE change:
//    head QPB 4 -> 8 (halves Wg re-read traffic and block count).
//  R8 showed the fused query epilogue spills the conv core's registers;
//  the lenet kernel below is byte-identical to the proven R2 version.
// ---------------------------------------------------------------------------

#define FEAT   400
#define HID    12
#define NCLS   10
#define SMAX   8
#define NQ_MAX 1024
#define NR_MAX (NQ_MAX * SMAX)
#define BDIM   224      // lenet block
#define QPB    8        // head queries per block  (R2 had 4 — only change)

__device__ float g_feat[NQ_MAX * FEAT];   // query features
__device__ float g_rx[NR_MAX * HID];      // ref projections (Wf·feat + bf)

typedef unsigned long long ull;

__device__ __forceinline__ ull pack2(float lo, float hi) {
    ull r; asm("mov.b64 %0, {%1, %2};" : "=l"(r) : "f"(lo), "f"(hi)); return r;
}
__device__ __forceinline__ void unpack2(ull v, float& lo, float& hi) {
    asm("mov.b64 {%0, %1}, %2;" : "=f"(lo), "=f"(hi) : "l"(v));
}
__device__ __forceinline__ ull fma2(ull a, ull b, ull c) {
    ull d; asm("fma.rn.f32x2 %0, %1, %2, %3;" : "=l"(d) : "l"(a), "l"(b), "l"(c));
    return d;
}
__device__ __forceinline__ ull ld64(const float2* p) {
    return *reinterpret_cast<const ull*>(p);
}

// ---------------------------------------------------------------------------
// LeNet feature kernel: one block per image  (== round 2, unchanged)
// ---------------------------------------------------------------------------
__global__ __launch_bounds__(BDIM, 3)
void lenet_kernel(const float* __restrict__ img,
                  const float* __restrict__ train,
                  const int*   __restrict__ refs,
                  const float* __restrict__ w1, const float* __restrict__ b1,
                  const float* __restrict__ w2, const float* __restrict__ b2,
                  const float* __restrict__ Wf, const float* __restrict__ bf,
                  int n_img)
{
    __shared__ float  s_img[3][32][32];       // 3072
    __shared__ float2 s_wp1[3][25][3];        // (oc2j, oc2j+1) pairs, 450 f
    __shared__ float2 s_wp2[6][25][8];        // 2400 f
    __shared__ float  s_b1[6];
    __shared__ float  s_b2[16];
    __shared__ float  s_p1[6][14][14];        // 1176
    __shared__ float  s_feat[FEAT];           // 400

    const int b = blockIdx.x;
    const int t = threadIdx.x;

    const float* src = (b < n_img)
        ? img + (size_t)b * 3072
        : train + (size_t)refs[b - n_img] * 3072;

    // load image: 768 float4
    {
        const float4* s4 = reinterpret_cast<const float4*>(src);
        float4* d4 = reinterpret_cast<float4*>(&s_img[0][0][0]);
        for (int i = t; i < 768; i += BDIM) d4[i] = s4[i];
    }
    // load packed weight pairs
    for (int i = t; i < 225; i += BDIM) {                // wp1: ic,k,j
        int ic = i / 75, r = i % 75, k = r / 3, j = r % 3;
        s_wp1[ic][k][j] = make_float2(w1[(2*j)     * 75 + ic * 25 + k],
                                      w1[(2*j + 1) * 75 + ic * 25 + k]);
    }
    for (int i = t; i < 1200; i += BDIM) {               // wp2: ic,k,j
        int ic = i / 200, r = i % 200, k = r / 8, j = r % 8;
        s_wp2[ic][k][j] = make_float2(w2[(2*j)     * 150 + ic * 25 + k],
                                      w2[(2*j + 1) * 150 + ic * 25 + k]);
    }
    if (t < 6)  s_b1[t] = b1[t];
    if (t < 16) s_b2[t] = b2[t];
    __syncthreads();

    // ---- conv1 + relu + maxpool2 : 6 x 14 x 14, FFMA2 over oc-pairs ----
    if (t < 196) {
        const int py = t / 14, px = t % 14;
        const int iy = 2 * py, ix = 2 * px;

        ull acc[3][4];
        #pragma unroll
        for (int j = 0; j < 3; j++) {
            ull bz = pack2(s_b1[2*j], s_b1[2*j + 1]);
            acc[j][0] = bz; acc[j][1] = bz; acc[j][2] = bz; acc[j][3] = bz;
        }
        #pragma unroll
        for (int ic = 0; ic < 3; ic++) {
            float in[6][6];
            #pragma unroll
            for (int r = 0; r < 6; r++)
                #pragma unroll
                for (int c = 0; c < 6; c++)
                    in[r][c] = s_img[ic][iy + r][ix + c];

            #pragma unroll
            for (int ky = 0; ky < 5; ky++) {
                #pragma unroll
                for (int kx = 0; kx < 5; kx++) {
                    const int k = ky * 5 + kx;
                    ull w0 = ld64(&s_wp1[ic][k][0]);
                    ull w1v = ld64(&s_wp1[ic][k][1]);
                    ull w2v = ld64(&s_wp1[ic][k][2]);

                    ull p = pack2(in[ky][kx], in[ky][kx]);
                    acc[0][0] = fma2(w0, p, acc[0][0]);
                    acc[1][0] = fma2(w1v, p, acc[1][0]);
                    acc[2][0] = fma2(w2v, p, acc[2][0]);

                    p = pack2(in[ky][kx+1], in[ky][kx+1]);
                    acc[0][1] = fma2(w0, p, acc[0][1]);
                    acc[1][1] = fma2(w1v, p, acc[1][1]);
                    acc[2][1] = fma2(w2v, p, acc[2][1]);

                    p = pack2(in[ky+1][kx], in[ky+1][kx]);
                    acc[0][2] = fma2(w0, p, acc[0][2]);
                    acc[1][2] = fma2(w1v, p, acc[1][2]);
                    acc[2][2] = fma2(w2v, p, acc[2][2]);

                    p = pack2(in[ky+1][kx+1], in[ky+1][kx+1]);
                    acc[0][3] = fma2(w0, p, acc[0][3]);
                    acc[1][3] = fma2(w1v, p, acc[1][3]);
                    acc[2][3] = fma2(w2v, p, acc[2][3]);
                }
            }
        }
        #pragma unroll
        for (int j = 0; j < 3; j++) {
            float a0l, a0h, a1l, a1h, a2l, a2h, a3l, a3h;
            unpack2(acc[j][0], a0l, a0h);
            unpack2(acc[j][1], a1l, a1h);
            unpack2(acc[j][2], a2l, a2h);
            unpack2(acc[j][3], a3l, a3h);
            float ml = fmaxf(fmaxf(a0l, a1l), fmaxf(a2l, a3l));
            float mh = fmaxf(fmaxf(a0h, a1h), fmaxf(a2h, a3h));
            s_p1[2*j    ][py][px] = fmaxf(ml, 0.0f);
            s_p1[2*j + 1][py][px] = fmaxf(mh, 0.0f);
        }
    }
    __syncthreads();

    // ---- conv2 + relu + maxpool2 : 16 x 5 x 5, (pos, oc-pair) tasks ----
    if (t < 200) {
        const int pos = t >> 3;        // 0..24
        const int j   = t & 7;         // oc pair 0..7
        const int py = pos / 5, px = pos % 5;
        const int iy = 2 * py, ix = 2 * px;

        ull a0, a1, a2, a3;
        {
            ull bz = pack2(s_b2[2*j], s_b2[2*j + 1]);
            a0 = bz; a1 = bz; a2 = bz; a3 = bz;
        }
        #pragma unroll
        for (int ic = 0; ic < 6; ic++) {
            float in[6][6];
            #pragma unroll
            for (int r = 0; r < 6; r++)
                #pragma unroll
                for (int c = 0; c < 6; c++)
                    in[r][c] = s_p1[ic][iy + r][ix + c];

            #pragma unroll
            for (int ky = 0; ky < 5; ky++) {
                #pragma unroll
                for (int kx = 0; kx < 5; kx++) {
                    ull w = ld64(&s_wp2[ic][ky * 5 + kx][j]);
                    a0 = fma2(w, pack2(in[ky  ][kx  ], in[ky  ][kx  ]), a0);
                    a1 = fma2(w, pack2(in[ky  ][kx+1], in[ky  ][kx+1]), a1);
                    a2 = fma2(w, pack2(in[ky+1][kx  ], in[ky+1][kx  ]), a2);
                    a3 = fma2(w, pack2(in[ky+1][kx+1], in[ky+1][kx+1]), a3);
                }
            }
        }
        float a0l,a0h,a1l,a1h,a2l,a2h,a3l,a3h;
        unpack2(a0, a0l, a0h); unpack2(a1, a1l, a1h);
        unpack2(a2, a2l, a2h); unpack2(a3, a3l, a3h);
        float ml = fmaxf(fmaxf(a0l, a1l), fmaxf(a2l, a3l));
        float mh = fmaxf(fmaxf(a0h, a1h), fmaxf(a2h, a3h));
        s_feat[(2*j    ) * 25 + pos] = fmaxf(ml, 0.0f);
        s_feat[(2*j + 1) * 25 + pos] = fmaxf(mh, 0.0f);
    }
    __syncthreads();

    if (b < n_img) {
        // query: store full feature vector
        float4* dst = reinterpret_cast<float4*>(g_feat + (size_t)b * FEAT);
        const float4* s4 = reinterpret_cast<const float4*>(s_feat);
        for (int i = t; i < 100; i += BDIM) dst[i] = s4[i];
    } else {
        // ref: project with Wf (12 warp-dots), store 12 floats only
        const int slot = b - n_img;
        const int warp = t >> 5, lane = t & 31;
        const float4* f4 = reinterpret_cast<const float4*>(s_feat);
        for (int d = warp; d < HID; d += (BDIM >> 5)) {
            const float4* w4 = reinterpret_cast<const float4*>(Wf + (size_t)d * FEAT);
            float acc = 0.0f;
            #pragma unroll
            for (int it = 0; it < 4; it++) {
                int e = lane + it * 32;
                if (e < 100) {
                    float4 a = f4[e], w = w4[e];
                    acc += a.x*w.x + a.y*w.y + a.z*w.z + a.w*w.w;
                }
            }
            #pragma unroll
            for (int o = 16; o > 0; o >>= 1)
                acc += __shfl_xor_sync(0xFFFFFFFFu, acc, o);
            if (lane == 0) g_rx[(size_t)slot * HID + d] = acc + bf[d];
        }
    }
}

// ---------------------------------------------------------------------------
// Head kernel: QPB queries per block, 256 threads (8 warps)
// ---------------------------------------------------------------------------
__global__ __launch_bounds__(256)
void head_kernel(const float* __restrict__ mem,
                 const int*   __restrict__ refs,
                 const float* __restrict__ Wf, const float* __restrict__ bf,
                 const float* __restrict__ Wg, const float* __restrict__ bg,
                 const float* __restrict__ Wm, const float* __restrict__ bm,
                 float* __restrict__ out, int n, int S)
{
    __shared__ float s_feat[QPB][FEAT];
    __shared__ float s_g[QPB][HID * NCLS];
    __shared__ float s_x[QPB][HID];
    __shared__ float s_rx[QPB][SMAX][HID];
    __shared__ float s_diff[QPB][SMAX][HID];
    __shared__ float s_norm[QPB][SMAX];
    __shared__ float s_mem[QPB][SMAX][NCLS];
    __shared__ float s_logit[QPB][SMAX][NCLS];
    __shared__ float s_wm[NCLS * NCLS];
    __shared__ float s_bm[NCLS];

    const int t = threadIdx.x;
    const int q0 = blockIdx.x * QPB;
    const int warp = t >> 5, lane = t & 31;

    // loads
    for (int i = t; i < QPB * 100; i += 256) {
        int ql = i / 100, e = i % 100;
        reinterpret_cast<float4*>(s_feat[ql])[e] =
            reinterpret_cast<const float4*>(g_feat + (size_t)(q0 + ql) * FEAT)[e];
    }
    for (int i = t; i < QPB * SMAX * NCLS; i += 256) {      // mem[refs]
        int ql = i / (SMAX * NCLS), r2 = i % (SMAX * NCLS);
        int s = r2 / NCLS, c = r2 % NCLS;
        int r = refs[(size_t)(q0 + ql) * S + s];
        s_mem[ql][s][c] = mem[(size_t)r * NCLS + c];
    }
    for (int i = t; i < QPB * SMAX * HID; i += 256) {       // ref projections
        int ql = i / (SMAX * HID), r2 = i % (SMAX * HID);
        int s = r2 / HID, h = r2 % HID;
        s_rx[ql][s][h] = g_rx[(size_t)((q0 + ql) * S + s) * HID + h];
    }
    if (t < NCLS * NCLS) s_wm[t] = Wm[t];
    if (t < NCLS) s_bm[t] = bm[t];
    __syncthreads();

    // 132 dot products (120 grad rows + 12 x rows), each for all QPB queries
    for (int d = warp; d < HID * NCLS + HID; d += 8) {
        const float* wrow; float bias;
        if (d < HID * NCLS) { wrow = Wg + (size_t)d * FEAT; bias = bg[d]; }
        else                { wrow = Wf + (size_t)(d - HID*NCLS) * FEAT; bias = bf[d - HID*NCLS]; }
        const float4* w4 = reinterpret_cast<const float4*>(wrow);
        float a[QPB];
        #pragma unroll
        for (int ql = 0; ql < QPB; ql++) a[ql] = 0.0f;
        #pragma unroll
        for (int it = 0; it < 4; it++) {
            int e = lane + it * 32;
            if (e < 100) {
                float4 w = w4[e];
                #pragma unroll
                for (int ql = 0; ql < QPB; ql++) {
                    float4 f = reinterpret_cast<const float4*>(s_feat[ql])[e];
                    a[ql] += f.x*w.x + f.y*w.y + f.z*w.z + f.w*w.w;
                }
            }
        }
        #pragma unroll
        for (int ql = 0; ql < QPB; ql++) {
            #pragma unroll
            for (int o = 16; o > 0; o >>= 1)
                a[ql] += __shfl_xor_sync(0xFFFFFFFFu, a[ql], o);
        }
        if (lane == 0) {
            #pragma unroll
            for (int ql = 0; ql < QPB; ql++) {
                float v = a[ql] + bias;
                if (d < HID * NCLS) s_g[ql][d] = v;
                else                s_x[ql][d - HID*NCLS] = v;
            }
        }
    }
    __syncthreads();

    // diff + norm
    if (t < QPB * SMAX) {
        int ql = t / SMAX, s = t % SMAX;
        float acc = 0.0f;
        #pragma unroll
        for (int h = 0; h < HID; h++) {
            float dd = s_x[ql][h] - s_rx[ql][s][h];
            s_diff[ql][s][h] = dd;
            acc += dd * dd;
        }
        s_norm[ql][s] = sqrtf(acc);
    }
    __syncthreads();

    // logits
    for (int i = t; i < QPB * SMAX * NCLS; i += 256) {
        int ql = i / (SMAX * NCLS), r2 = i % (SMAX * NCLS);
        int s = r2 / NCLS, c = r2 % NCLS;
        float acc = s_bm[c];
        #pragma unroll
        for (int jj = 0; jj < NCLS; jj++)
            acc += s_wm[c * NCLS + jj] * s_mem[ql][s][jj];
        #pragma unroll
        for (int h = 0; h < HID; h++)
            acc += s_diff[ql][s][h] * s_g[ql][h * NCLS + c];
        s_logit[ql][s][c] = acc;
    }
    __syncthreads();

    // softmax(-norm) weighted combine
    for (int i = t; i < QPB * NCLS; i += 256) {
        int ql = i / NCLS, c = i % NCLS;
        float mx = -1e30f;
        for (int s = 0; s < S; s++) mx = fmaxf(mx, -s_norm[ql][s]);
        float se = 0.0f, acc = 0.0f;
        for (int s = 0; s < S; s++) {
            float e = expf(-s_norm[ql][s] - mx);
            se += e;
            acc += e * s_logit[ql][s][c];
        }
        out[(size_t)(q0 + ql) * NCLS + c] = acc / se;
    }
}

// ---------------------------------------------------------------------------
// launcher
// ---------------------------------------------------------------------------
extern "C" void kernel_launch(void* const* d_in, const int* in_sizes, int n_in,
                              void* d_out, int out_size)
{
    const float* img   = (const float*)d_in[0];
    const float* train = (const float*)d_in[1];
    const float* mem   = (const float*)d_in[2];
    const float* w1    = (const float*)d_in[3];
    const float* b1    = (const float*)d_in[4];
    const float* w2    = (const float*)d_in[5];
    const float* b2    = (const float*)d_in[6];
    const float* Wf    = (const float*)d_in[7];
    const float* bf    = (const float*)d_in[8];
    const float* Wg    = (const float*)d_in[9];
    const float* bg    = (const float*)d_in[10];
    const float* Wm    = (const float*)d_in[11];
    const float* bm    = (const float*)d_in[12];
    // d_in[13] = idx : unused by the reference computation
    const int*   refs  = (const int*)d_in[14];

    const int n = in_sizes[0] / (3 * 32 * 32);   // 1024
    const int S = in_sizes[14] / n;              // 8
    if (n > NQ_MAX || S != SMAX || (n % QPB) != 0) return;

    const int ntot = n + n * S;                  // 9216
    lenet_kernel<<<ntot, BDIM>>>(img, train, refs, w1, b1, w2, b2, Wf, bf, n);
    head_kernel<<<n / QPB, 256>>>(mem, refs, Wf, bf, Wg, bg, Wm, bm,
                                  (float*)d_out, n, S);
}